// round 15
// baseline (speedup 1.0000x reference)
#include <cuda_runtime.h>
#include <cuda_bf16.h>

// Shapes (fixed by the problem)
#define BB  8
#define CC  512
#define LL  2048
#define CQ  64
#define SCALE 0.125f   // CQK^-0.5 (exact power of 2; folded into q at qkv epilogue)

typedef __nv_bfloat16  bf16;
typedef __nv_bfloat162 bf162;

// ---------------------------------------------------------------------------
// Scratch (static __device__ arrays — no allocation anywhere)
// ---------------------------------------------------------------------------
__device__ bf16 g_xb[(size_t)BB * CC * LL];        // 16.8 MB  x in bf16
__device__ bf16 g_wqk[(size_t)128 * CC];           // 128 KB  [Wq;Wk] stacked
__device__ bf16 g_wv[(size_t)CC * CC];             // 512 KB
__device__ bf16 g_wo[(size_t)CC * CC];             // 512 KB
__device__ bf16 g_qb[(size_t)BB * CQ * LL];        // 2 MB   (pre-scaled by SCALE)
__device__ bf16 g_kb[(size_t)BB * CQ * LL];        // 2 MB
__device__ bf16 g_vb[(size_t)BB * CC * LL];        // 16.8 MB
__device__ bf16 g_av2[(size_t)BB * LL * CC];       // 16.8 MB  attention out, [b][l][c]

// ---------------------------------------------------------------------------
// Helpers
// ---------------------------------------------------------------------------
__device__ __forceinline__ void cp16(void* dst_smem, const void* src) {
    unsigned d = (unsigned)__cvta_generic_to_shared(dst_smem);
    asm volatile("cp.async.cg.shared.global [%0], [%1], 16;" :: "r"(d), "l"(src));
}
#define CP_COMMIT() asm volatile("cp.async.commit_group;")
#define CP_WAIT(N)  asm volatile("cp.async.wait_group " #N ";")

__device__ __forceinline__ void ldsm_x4(unsigned* r, unsigned s) {
    asm volatile("ldmatrix.sync.aligned.m8n8.x4.shared.b16 {%0,%1,%2,%3}, [%4];"
        : "=r"(r[0]), "=r"(r[1]), "=r"(r[2]), "=r"(r[3]) : "r"(s));
}
__device__ __forceinline__ void ldsm_x2(unsigned* r, unsigned s) {
    asm volatile("ldmatrix.sync.aligned.m8n8.x2.shared.b16 {%0,%1}, [%2];"
        : "=r"(r[0]), "=r"(r[1]) : "r"(s));
}
__device__ __forceinline__ void ldsm_x4t(unsigned* r, unsigned s) {
    asm volatile("ldmatrix.sync.aligned.m8n8.x4.trans.shared.b16 {%0,%1,%2,%3}, [%4];"
        : "=r"(r[0]), "=r"(r[1]), "=r"(r[2]), "=r"(r[3]) : "r"(s));
}
__device__ __forceinline__ void ldsm_x2t(unsigned* r, unsigned s) {
    asm volatile("ldmatrix.sync.aligned.m8n8.x2.trans.shared.b16 {%0,%1}, [%2];"
        : "=r"(r[0]), "=r"(r[1]) : "r"(s));
}

// D += A(16x16 row) * B(16x8 col), fp32 accum.
__device__ __forceinline__ void mma_bf16(float* c, const unsigned* a, const unsigned* b) {
    asm volatile(
        "mma.sync.aligned.m16n8k16.row.col.f32.bf16.bf16.f32 "
        "{%0,%1,%2,%3}, {%4,%5,%6,%7}, {%8,%9}, {%0,%1,%2,%3};"
        : "+f"(c[0]), "+f"(c[1]), "+f"(c[2]), "+f"(c[3])
        : "r"(a[0]), "r"(a[1]), "r"(a[2]), "r"(a[3]), "r"(b[0]), "r"(b[1]));
}

// pack two fp32 into one bf16x2 reg: low = lo, high = hi
__device__ __forceinline__ unsigned packbf(float lo, float hi) {
    unsigned d;
    asm("cvt.rn.bf16x2.f32 %0, %1, %2;" : "=r"(d) : "f"(hi), "f"(lo));
    return d;
}

// Frag maps (lane = 4g+t):
//  A: a0=A[g][2t,2t+1] a1=A[g+8][2t..] a2=A[g][8+2t..] a3=A[g+8][8+2t..]
//  B: b0=B[2t,2t+1][g] b1=B[8+2t..][g]   (B indexed [k][n])
//  C: c0=C[g][2t] c1=C[g][2t+1] c2=C[g+8][2t] c3=C[g+8][2t+1]
// C->A identity: two adjacent n8 C tiles == one k16 A frag (the FA2 trick).
// Smem strides 72/136 bf16 = 9/17 x16B units -> rows mod 8 distinct, LDSM-safe.

// ---------------------------------------------------------------------------
// Kernel 0: fp32 -> bf16 conversion of x and weights. Wq/Wk stacked into g_wqk.
// ---------------------------------------------------------------------------
#define NX  ((size_t)BB * CC * LL)
#define NWQ ((size_t)CQ * CC)
#define NWV ((size_t)CC * CC)
#define CVT_PAIRS ((NX + 2 * NWQ + 2 * NWV) / 2)
__global__ __launch_bounds__(256) void cvt_kernel(
    const float* __restrict__ x,  const float* __restrict__ Wq,
    const float* __restrict__ Wk, const float* __restrict__ Wv,
    const float* __restrict__ Wo)
{
    size_t i = ((size_t)blockIdx.x * 256 + threadIdx.x) * 2;
    if (i < NX) {
        *(bf162*)&g_xb[i] = __float22bfloat162_rn(*(const float2*)&x[i]); return;
    }
    i -= NX;
    if (i < NWQ) { *(bf162*)&g_wqk[i] = __float22bfloat162_rn(*(const float2*)&Wq[i]); return; }
    i -= NWQ;
    if (i < NWQ) { *(bf162*)&g_wqk[NWQ + i] = __float22bfloat162_rn(*(const float2*)&Wk[i]); return; }
    i -= NWQ;
    if (i < NWV) { *(bf162*)&g_wv[i] = __float22bfloat162_rn(*(const float2*)&Wv[i]); return; }
    i -= NWV;
    if (i < NWV) { *(bf162*)&g_wo[i] = __float22bfloat162_rn(*(const float2*)&Wo[i]); }
}

// ---------------------------------------------------------------------------
// Kernel 1: fused QKV projection v2. Block 128m x 128n, k-chunk 64, 3-stage.
// rt 0: rows = [Wq;Wk] (warp wm=0 -> q with SCALE, wm=64 -> k); rt 1..4: Wv.
//   As[128][72] ([m][k])  A via ldsm_x4    |  Bs[64][136] ([k][n])  B via ldsm_x2t
// ---------------------------------------------------------------------------
#define QKV_A (128 * 72)
#define QKV_B (64 * 136)
#define QKV_STAGES 3
#define QKV_SMEM ((QKV_STAGES * (QKV_A + QKV_B)) * 2)
__global__ __launch_bounds__(256) void qkv_kernel(
    const float* __restrict__ bq, const float* __restrict__ bk,
    const float* __restrict__ bv)
{
    extern __shared__ bf16 sm[];
    bf16* As = sm;
    bf16* Bs = sm + QKV_STAGES * QKV_A;

    const int b  = blockIdx.z;
    const int rt = blockIdx.y;           // 0..4
    const int l0 = blockIdx.x * 128;

    const bf16* W = (rt == 0) ? g_wqk : g_wv + (size_t)(rt - 1) * 128 * CC;

    const int tid = threadIdx.x, w = tid >> 5, lane = tid & 31;
    const int g = lane >> 2, t = lane & 3;
    const int wm = (w >> 2) * 64, wn = (w & 3) * 32;
    const int l15 = lane & 15, hi = lane >> 4;
    const bf16* xb = g_xb + (size_t)b * CC * LL;
    const unsigned smA = (unsigned)__cvta_generic_to_shared(As);
    const unsigned smB = (unsigned)__cvta_generic_to_shared(Bs);

    float acc[4][4][4] = {};

    auto stage = [&](int buf, int k0) {
        bf16* Ab = As + buf * QKV_A;
        bf16* Bb = Bs + buf * QKV_B;
        #pragma unroll
        for (int i = 0; i < 4; ++i) {   // 128m x 64k W tile
            int idx = tid + i * 256, m = idx >> 3, k8 = (idx & 7) * 8;
            cp16(Ab + m * 72 + k8, W + (size_t)m * CC + k0 + k8);
        }
        #pragma unroll
        for (int i = 0; i < 4; ++i) {   // 64k x 128n x tile
            int idx = tid + i * 256, k = idx >> 4, n8 = (idx & 15) * 8;
            cp16(Bb + k * 136 + n8, xb + (size_t)(k0 + k) * LL + l0 + n8);
        }
        CP_COMMIT();
    };

    const int NIT = CC / 64;   // 8
    stage(0, 0); stage(1, 64);
    int ld = 2, cb = 0;
    for (int it = 0; it < NIT; ++it) {
        if (it < NIT - 2) { CP_WAIT(1); } else { CP_WAIT(0); }
        __syncthreads();
        if (it + 2 < NIT) { stage(ld, (it + 2) * 64); ld = (ld == 2) ? 0 : ld + 1; }
        const unsigned a0 = smA + (unsigned)(cb * QKV_A) * 2;
        const unsigned b0a = smB + (unsigned)(cb * QKV_B) * 2;
        cb = (cb == 2) ? 0 : cb + 1;
        #pragma unroll
        for (int ks = 0; ks < 4; ++ks) {
            const int kk = ks * 16;
            unsigned af[4][4], bf[4][2];
            #pragma unroll
            for (int mi = 0; mi < 4; ++mi)
                ldsm_x4(af[mi], a0 + (unsigned)((wm + mi * 16 + l15) * 72 + kk) * 2 + hi * 16);
            #pragma unroll
            for (int ni = 0; ni < 4; ++ni)
                ldsm_x2t(bf[ni], b0a + (unsigned)((kk + l15) * 136 + wn + ni * 8) * 2);
            #pragma unroll
            for (int mi = 0; mi < 4; ++mi)
                #pragma unroll
                for (int ni = 0; ni < 4; ++ni)
                    mma_bf16(acc[mi][ni], af[mi], bf[ni]);
        }
    }

    // epilogue: route per warp-row-half
    bf16* o; const float* bi; float osc; int gr0;
    if (rt == 0) {
        if (wm == 0) { o = g_qb + (size_t)b * CQ * LL; bi = bq; osc = SCALE; gr0 = 0; }
        else         { o = g_kb + (size_t)b * CQ * LL; bi = bk; osc = 1.f;   gr0 = -64; }
    } else {
        o = g_vb + (size_t)b * CC * LL; bi = bv; osc = 1.f; gr0 = (rt - 1) * 128;
    }
    #pragma unroll
    for (int mi = 0; mi < 4; ++mi) {
        int r0r = gr0 + wm + mi * 16 + g;
        int r1r = r0r + 8;
        float b0v = bi[r0r], b1v = bi[r1r];
        #pragma unroll
        for (int ni = 0; ni < 4; ++ni) {
            int col = l0 + wn + ni * 8 + 2 * t;
            *(bf162*)&o[(size_t)r0r * LL + col] =
                __floats2bfloat162_rn((acc[mi][ni][0] + b0v) * osc, (acc[mi][ni][1] + b0v) * osc);
            *(bf162*)&o[(size_t)r1r * LL + col] =
                __floats2bfloat162_rn((acc[mi][ni][2] + b1v) * osc, (acc[mi][ni][3] + b1v) * osc);
        }
    }
}

// ---------------------------------------------------------------------------
// Kernel 2: FUSED flash attention v3 — v1 dataflow (all warps do GEMM1 +
// softmax + GEMM2, no phase split, no smem P), resized to avoid spills:
// Block 64q x 256c (grid 32 q-tiles x 2 c-halves x 8 b). 8 warps =
// 4 q-groups x 2 c-groups; warp = 16q x 128c, k-tile 64 (2x GEMM1 redundancy).
// Regs/thread ~150 (acc 64 + sf 32 + paf 16 + misc).
// Smem: Qs[64][72] @0 | Ks[2][64][72] @4608 | Vs[2][256][72] @13824. 2-stage.
// ---------------------------------------------------------------------------
#define FA_SMEM (50688 * 2)
__global__ __launch_bounds__(256, 1) void fa_kernel()
{
    extern __shared__ bf16 sm[];
    bf16* Qs = sm;
    bf16* Ks = sm + 4608;
    bf16* Vs = sm + 13824;

    const int b  = blockIdx.z;
    const int q0 = blockIdx.x * 64;
    const int c0 = blockIdx.y * 256;

    const int tid = threadIdx.x, w = tid >> 5, lane = tid & 31;
    const int g = lane >> 2, t = lane & 3;
    const int qg = (w & 3) * 16;      // warp's q-group rows
    const int ch = (w >> 2) * 128;    // warp's c-range within the 256-c half
    const bf16* qb = g_qb + (size_t)b * CQ * LL;
    const bf16* kb = g_kb + (size_t)b * CQ * LL;
    const bf16* vb = g_vb + (size_t)b * CC * LL + (size_t)c0 * LL;

    const unsigned smQ = (unsigned)__cvta_generic_to_shared(Qs);
    const unsigned smK = (unsigned)__cvta_generic_to_shared(Ks);
    const unsigned smV = (unsigned)__cvta_generic_to_shared(Vs);

    // per-lane ldsm address components (patterns validated in R11/R12)
    const int aq_row = (lane >> 4) * 8 + (lane & 7);        // Q x4t row(c)
    const int aq_col = qg + ((lane >> 3) & 1) * 8;          // Q x4t col(q)
    const int bk_row = ((lane >> 3) & 1) * 8 + (lane & 7);  // K x4t row(c)
    const int bk_csel = (lane >> 4) * 8;                    // K x4t +col(k)
    const int v_row  = ((lane >> 4) & 1) * 8 + (lane & 7);  // V x4 row(c) in 16-grp
    const int v_csel = ((lane >> 3) & 1) * 8;               // V x4 +col(k)

    // load Q tile [c=64][q=64] once
    #pragma unroll
    for (int i = 0; i < 2; ++i) {
        int idx = tid + i * 256, c = idx >> 3, q8 = (idx & 7) * 8;
        cp16(Qs + c * 72 + q8, qb + (size_t)c * LL + q0 + q8);
    }
    CP_COMMIT();

    auto stage = [&](int buf, int kt) {
        bf16* Kb = Ks + buf * 4608;
        bf16* Vb = Vs + buf * 18432;
        const int k0 = kt * 64;
        #pragma unroll
        for (int i = 0; i < 2; ++i) {         // K: 64c x 64k
            int idx = tid + i * 256, c = idx >> 3, k8 = (idx & 7) * 8;
            cp16(Kb + c * 72 + k8, kb + (size_t)c * LL + k0 + k8);
        }
        #pragma unroll
        for (int i = 0; i < 8; ++i) {         // V: 256c x 64k
            int idx = tid + i * 256, c = idx >> 3, k8 = (idx & 7) * 8;
            cp16(Vb + c * 72 + k8, vb + (size_t)c * LL + k0 + k8);
        }
        CP_COMMIT();
    };
    stage(0, 0); stage(1, 1);

    float acc[16][4] = {};
    float mx0 = -1e30f, mx1 = -1e30f, ls0 = 0.f, ls1 = 0.f;

    const int NIT = LL / 64;   // 32
    for (int it = 0; it < NIT; ++it) {
        if (it < NIT - 1) { CP_WAIT(1); } else { CP_WAIT(0); }
        __syncthreads();
        const int cb = it & 1;
        const unsigned k0s = smK + (unsigned)(cb * 4608) * 2;
        const unsigned v0s = smV + (unsigned)(cb * 18432) * 2;

        // ---- GEMM1: S[16q][64k] (every warp; 2x redundancy across c-groups) ----
        float sf[8][4];
        #pragma unroll
        for (int ni = 0; ni < 8; ++ni)
            #pragma unroll
            for (int j = 0; j < 4; ++j) sf[ni][j] = 0.f;
        #pragma unroll
        for (int cs = 0; cs < 4; ++cs) {
            unsigned af[4];
            ldsm_x4t(af, smQ + (unsigned)((cs * 16 + aq_row) * 72 + aq_col) * 2);
            #pragma unroll
            for (int nj = 0; nj < 4; ++nj) {
                unsigned bq4[4];
                ldsm_x4t(bq4, k0s + (unsigned)((cs * 16 + bk_row) * 72 + nj * 16 + bk_csel) * 2);
                mma_bf16(sf[2 * nj],     af, bq4);
                mma_bf16(sf[2 * nj + 1], af, bq4 + 2);
            }
        }

        // ---- online softmax (rows qg+g, qg+g+8) ----
        float cm0 = -1e30f, cm1 = -1e30f;
        #pragma unroll
        for (int ni = 0; ni < 8; ++ni) {
            cm0 = fmaxf(cm0, fmaxf(sf[ni][0], sf[ni][1]));
            cm1 = fmaxf(cm1, fmaxf(sf[ni][2], sf[ni][3]));
        }
        cm0 = fmaxf(cm0, __shfl_xor_sync(0xffffffffu, cm0, 1));
        cm0 = fmaxf(cm0, __shfl_xor_sync(0xffffffffu, cm0, 2));
        cm1 = fmaxf(cm1, __shfl_xor_sync(0xffffffffu, cm1, 1));
        cm1 = fmaxf(cm1, __shfl_xor_sync(0xffffffffu, cm1, 2));
        const float mn0 = fmaxf(mx0, cm0), mn1 = fmaxf(mx1, cm1);
        const float f0 = __expf(mx0 - mn0), f1 = __expf(mx1 - mn1);
        mx0 = mn0; mx1 = mn1;

        float s0 = 0.f, s1 = 0.f;
        #pragma unroll
        for (int ni = 0; ni < 8; ++ni) {
            sf[ni][0] = __expf(sf[ni][0] - mn0);
            sf[ni][1] = __expf(sf[ni][1] - mn0);
            sf[ni][2] = __expf(sf[ni][2] - mn1);
            sf[ni][3] = __expf(sf[ni][3] - mn1);
            s0 += sf[ni][0] + sf[ni][1];
            s1 += sf[ni][2] + sf[ni][3];
        }
        s0 += __shfl_xor_sync(0xffffffffu, s0, 1);
        s0 += __shfl_xor_sync(0xffffffffu, s0, 2);
        s1 += __shfl_xor_sync(0xffffffffu, s1, 1);
        s1 += __shfl_xor_sync(0xffffffffu, s1, 2);
        ls0 = ls0 * f0 + s0;
        ls1 = ls1 * f1 + s1;

        // rescale acc
        #pragma unroll
        for (int ni = 0; ni < 16; ++ni) {
            acc[ni][0] *= f0; acc[ni][1] *= f0;
            acc[ni][2] *= f1; acc[ni][3] *= f1;
        }

        // pack P: C-frags -> A-frags (in register)
        unsigned paf[4][4];
        #pragma unroll
        for (int ks = 0; ks < 4; ++ks) {
            paf[ks][0] = packbf(sf[2 * ks][0],     sf[2 * ks][1]);
            paf[ks][1] = packbf(sf[2 * ks][2],     sf[2 * ks][3]);
            paf[ks][2] = packbf(sf[2 * ks + 1][0], sf[2 * ks + 1][1]);
            paf[ks][3] = packbf(sf[2 * ks + 1][2], sf[2 * ks + 1][3]);
        }

        // ---- GEMM2: acc[16q][128c] += P[16q][64k] * V^T ----
        #pragma unroll
        for (int ks = 0; ks < 4; ++ks) {
            const int kk = ks * 16;
            #pragma unroll
            for (int ci = 0; ci < 8; ++ci) {
                unsigned vf[4];
                ldsm_x4(vf, v0s + (unsigned)((ch + ci * 16 + v_row) * 72 + kk + v_csel) * 2);
                mma_bf16(acc[2 * ci],     paf[ks], vf);
                mma_bf16(acc[2 * ci + 1], paf[ks], vf + 2);
            }
        }
        __syncthreads();
        if (it + 2 < NIT) stage(cb, it + 2);
    }

    // ---- epilogue: divide by l, write av [b][l][c] ----
    const float i0 = 1.0f / ls0, i1 = 1.0f / ls1;
    const int row0 = q0 + qg + g, row1 = row0 + 8;
    bf16* ob0 = g_av2 + ((size_t)b * LL + row0) * CC;
    bf16* ob1 = g_av2 + ((size_t)b * LL + row1) * CC;
    #pragma unroll
    for (int ni = 0; ni < 16; ++ni) {
        int col = c0 + ch + ni * 8 + 2 * t;
        *(bf162*)&ob0[col] = __floats2bfloat162_rn(acc[ni][0] * i0, acc[ni][1] * i0);
        *(bf162*)&ob1[col] = __floats2bfloat162_rn(acc[ni][2] * i1, acc[ni][3] * i1);
    }
}

// ---------------------------------------------------------------------------
// Kernel 3: O projection + bias + residual. k-chunk 64 (8 iters), 3-stage.
//   As[128][72] (Wo [o][c])  ldsm_x4  |  Bs[128][72] (av [l][c])  ldsm_x2
// ---------------------------------------------------------------------------
#define OP_A (128 * 72)
#define OP_B (128 * 72)
#define OP_STAGES 3
#define OP_SMEM ((OP_STAGES * (OP_A + OP_B)) * 2)
__global__ __launch_bounds__(256) void outproj_kernel(
    const float* __restrict__ x,
    const float* __restrict__ bo, float* __restrict__ out)
{
    extern __shared__ bf16 sm[];
    bf16* As = sm;
    bf16* Bs = sm + OP_STAGES * OP_A;

    const int b  = blockIdx.z;
    const int r0 = blockIdx.y * 128;
    const int l0 = blockIdx.x * 128;

    const int tid = threadIdx.x, w = tid >> 5, lane = tid & 31;
    const int g = lane >> 2, t = lane & 3;
    const int wm = (w >> 2) * 64, wn = (w & 3) * 32;
    const int l15 = lane & 15, hi = lane >> 4;
    const int l7 = lane & 7, b8 = ((lane >> 3) & 1) * 8;
    const bf16* avb = g_av2 + (size_t)b * LL * CC;
    const unsigned smA = (unsigned)__cvta_generic_to_shared(As);
    const unsigned smB = (unsigned)__cvta_generic_to_shared(Bs);

    float acc[4][4][4] = {};

    auto stage = [&](int buf, int k0) {
        bf16* Ab = As + buf * OP_A;
        bf16* Bb = Bs + buf * OP_B;
        #pragma unroll
        for (int i = 0; i < 4; ++i) {   // 128o x 64c Wo tile
            int idx = tid + i * 256, m = idx >> 3, k8 = (idx & 7) * 8;
            cp16(Ab + m * 72 + k8, g_wo + (size_t)(r0 + m) * CC + k0 + k8);
        }
        #pragma unroll
        for (int i = 0; i < 4; ++i) {   // 128l x 64c av tile
            int idx = tid + i * 256, l = idx >> 3, c8 = (idx & 7) * 8;
            cp16(Bb + l * 72 + c8, avb + (size_t)(l0 + l) * CC + k0 + c8);
        }
        CP_COMMIT();
    };

    const int NIT = CC / 64;   // 8
    stage(0, 0); stage(1, 64);
    int ld = 2, cb = 0;
    for (int it = 0; it < NIT; ++it) {
        if (it < NIT - 2) { CP_WAIT(1); } else { CP_WAIT(0); }
        __syncthreads();
        if (it + 2 < NIT) { stage(ld, (it + 2) * 64); ld = (ld == 2) ? 0 : ld + 1; }
        const unsigned a0 = smA + (unsigned)(cb * OP_A) * 2;
        const unsigned b0a = smB + (unsigned)(cb * OP_B) * 2;
        cb = (cb == 2) ? 0 : cb + 1;
        #pragma unroll
        for (int ks = 0; ks < 4; ++ks) {
            const int kk = ks * 16;
            unsigned af[4][4], bf[4][2];
            #pragma unroll
            for (int mi = 0; mi < 4; ++mi)
                ldsm_x4(af[mi], a0 + (unsigned)((wm + mi * 16 + l15) * 72 + kk) * 2 + hi * 16);
            #pragma unroll
            for (int ni = 0; ni < 4; ++ni)
                ldsm_x2(bf[ni], b0a + (unsigned)((wn + ni * 8 + l7) * 72 + kk + b8) * 2);
            #pragma unroll
            for (int mi = 0; mi < 4; ++mi)
                #pragma unroll
                for (int ni = 0; ni < 4; ++ni)
                    mma_bf16(acc[mi][ni], af[mi], bf[ni]);
        }
    }

    #pragma unroll
    for (int mi = 0; mi < 4; ++mi) {
        int ch0 = r0 + wm + mi * 16 + g;
        int ch1 = ch0 + 8;
        float b0v = bo[ch0], b1v = bo[ch1];
        #pragma unroll
        for (int ni = 0; ni < 4; ++ni) {
            int col = l0 + wn + ni * 8 + 2 * t;
            size_t off0 = (size_t)b * CC * LL + (size_t)ch0 * LL + col;
            size_t off1 = (size_t)b * CC * LL + (size_t)ch1 * LL + col;
            float2 x0 = *(const float2*)&x[off0];
            float2 x1 = *(const float2*)&x[off1];
            *(float2*)&out[off0] = make_float2(acc[mi][ni][0] + b0v + x0.x,
                                               acc[mi][ni][1] + b0v + x0.y);
            *(float2*)&out[off1] = make_float2(acc[mi][ni][2] + b1v + x1.x,
                                               acc[mi][ni][3] + b1v + x1.y);
        }
    }
}

// ---------------------------------------------------------------------------
// Launch: 4 kernels on one stream, graph-capturable, no allocations.
// ---------------------------------------------------------------------------
extern "C" void kernel_launch(void* const* d_in, const int* in_sizes, int n_in,
                              void* d_out, int out_size)
{
    (void)in_sizes; (void)n_in; (void)out_size;
    const float* x  = (const float*)d_in[0];
    const float* Wq = (const float*)d_in[1];
    const float* bq = (const float*)d_in[2];
    const float* Wk = (const float*)d_in[3];
    const float* bk = (const float*)d_in[4];
    const float* Wv = (const float*)d_in[5];
    const float* bv = (const float*)d_in[6];
    const float* Wo = (const float*)d_in[7];
    const float* bo = (const float*)d_in[8];
    float* out = (float*)d_out;

    cudaFuncSetAttribute(qkv_kernel,     cudaFuncAttributeMaxDynamicSharedMemorySize, QKV_SMEM);
    cudaFuncSetAttribute(fa_kernel,      cudaFuncAttributeMaxDynamicSharedMemorySize, FA_SMEM);
    cudaFuncSetAttribute(outproj_kernel, cudaFuncAttributeMaxDynamicSharedMemorySize, OP_SMEM);

    dim3 blk(256);
    cvt_kernel    <<<(unsigned)((CVT_PAIRS + 255) / 256), blk>>>(x, Wq, Wk, Wv, Wo);
    qkv_kernel    <<<dim3(LL / 128, 5,        BB), blk, QKV_SMEM>>>(bq, bk, bv);
    fa_kernel     <<<dim3(LL / 64,  2,        BB), blk, FA_SMEM>>>();
    outproj_kernel<<<dim3(LL / 128, CC / 128, BB), blk, OP_SMEM>>>(x, bo, out);
}

// round 16
// speedup vs baseline: 1.7564x; 1.7564x over previous
#include <cuda_runtime.h>
#include <cuda_bf16.h>

// Shapes (fixed by the problem)
#define BB  8
#define CC  512
#define LL  2048
#define CQ  64
#define SCALE 0.125f   // CQK^-0.5 (exact power of 2; folded into q at qkv epilogue)

typedef __nv_bfloat16  bf16;
typedef __nv_bfloat162 bf162;

// ---------------------------------------------------------------------------
// Scratch (static __device__ arrays — no allocation anywhere)
// ---------------------------------------------------------------------------
__device__ bf16 g_xb[(size_t)BB * CC * LL];        // 16.8 MB  x in bf16
__device__ bf16 g_wq[CQ * CC], g_wk[CQ * CC];      // 64 KB each
__device__ bf16 g_wv[(size_t)CC * CC];             // 512 KB
__device__ bf16 g_wo[(size_t)CC * CC];             // 512 KB
__device__ bf16 g_qb[(size_t)BB * CQ * LL];        // 2 MB   (pre-scaled by SCALE)
__device__ bf16 g_kb[(size_t)BB * CQ * LL];        // 2 MB
__device__ bf16 g_vb[(size_t)BB * CC * LL];        // 16.8 MB
__device__ bf16 g_av2[(size_t)BB * LL * CC];       // 16.8 MB  attention out, [b][l][c]

// ---------------------------------------------------------------------------
// Helpers
// ---------------------------------------------------------------------------
__device__ __forceinline__ void cp16(void* dst_smem, const void* src) {
    unsigned d = (unsigned)__cvta_generic_to_shared(dst_smem);
    asm volatile("cp.async.cg.shared.global [%0], [%1], 16;" :: "r"(d), "l"(src));
}
#define CP_COMMIT() asm volatile("cp.async.commit_group;")
#define CP_WAIT(N)  asm volatile("cp.async.wait_group " #N ";")

__device__ __forceinline__ void ldsm_x4(unsigned* r, unsigned s) {
    asm volatile("ldmatrix.sync.aligned.m8n8.x4.shared.b16 {%0,%1,%2,%3}, [%4];"
        : "=r"(r[0]), "=r"(r[1]), "=r"(r[2]), "=r"(r[3]) : "r"(s));
}
__device__ __forceinline__ void ldsm_x4t(unsigned* r, unsigned s) {
    asm volatile("ldmatrix.sync.aligned.m8n8.x4.trans.shared.b16 {%0,%1,%2,%3}, [%4];"
        : "=r"(r[0]), "=r"(r[1]), "=r"(r[2]), "=r"(r[3]) : "r"(s));
}

// D += A(16x16 row) * B(16x8 col), fp32 accum.
__device__ __forceinline__ void mma_bf16(float* c, const unsigned* a, const unsigned* b) {
    asm volatile(
        "mma.sync.aligned.m16n8k16.row.col.f32.bf16.bf16.f32 "
        "{%0,%1,%2,%3}, {%4,%5,%6,%7}, {%8,%9}, {%0,%1,%2,%3};"
        : "+f"(c[0]), "+f"(c[1]), "+f"(c[2]), "+f"(c[3])
        : "r"(a[0]), "r"(a[1]), "r"(a[2]), "r"(a[3]), "r"(b[0]), "r"(b[1]));
}

// pack two fp32 into one bf16x2 reg: low = lo, high = hi
__device__ __forceinline__ unsigned packbf(float lo, float hi) {
    unsigned d;
    asm("cvt.rn.bf16x2.f32 %0, %1, %2;" : "=r"(d) : "f"(hi), "f"(lo));
    return d;
}

// Frag maps (lane = 4g+t):
//  A: a0=A[g][2t,2t+1] a1=A[g+8][2t..] a2=A[g][8+2t..] a3=A[g+8][8+2t..]
//  B: b0=B[2t,2t+1][g] b1=B[8+2t..][g]   (B indexed [k][n])
//  C: c0=C[g][2t] c1=C[g][2t+1] c2=C[g+8][2t] c3=C[g+8][2t+1]
// C->A identity: two adjacent n8 C tiles == one k16 A frag (the FA2 trick).
// Merged B ldsm_x4: mats {0,1} = fragment ni (cols k, k+8), mats {2,3} =
// fragment ni+1 — lane bit4 selects the n8 group, bit3 the k8 column.
// Smem strides 40/72/136 bf16 = 5/9/17 x16B units -> rows mod 8 distinct, LDSM-safe.

// ---------------------------------------------------------------------------
// Kernel 0: fp32 -> bf16 conversion of x and weights (once per launch)
// ---------------------------------------------------------------------------
#define NX  ((size_t)BB * CC * LL)
#define NWQ ((size_t)CQ * CC)
#define NWV ((size_t)CC * CC)
#define CVT_PAIRS ((NX + 2 * NWQ + 2 * NWV) / 2)
__global__ __launch_bounds__(256) void cvt_kernel(
    const float* __restrict__ x,  const float* __restrict__ Wq,
    const float* __restrict__ Wk, const float* __restrict__ Wv,
    const float* __restrict__ Wo)
{
    size_t i = ((size_t)blockIdx.x * 256 + threadIdx.x) * 2;
    if (i < NX) {
        *(bf162*)&g_xb[i] = __float22bfloat162_rn(*(const float2*)&x[i]); return;
    }
    i -= NX;
    if (i < NWQ) { *(bf162*)&g_wq[i] = __float22bfloat162_rn(*(const float2*)&Wq[i]); return; }
    i -= NWQ;
    if (i < NWQ) { *(bf162*)&g_wk[i] = __float22bfloat162_rn(*(const float2*)&Wk[i]); return; }
    i -= NWQ;
    if (i < NWV) { *(bf162*)&g_wv[i] = __float22bfloat162_rn(*(const float2*)&Wv[i]); return; }
    i -= NWV;
    if (i < NWV) { *(bf162*)&g_wo[i] = __float22bfloat162_rn(*(const float2*)&Wo[i]); }
}

// ---------------------------------------------------------------------------
// Kernel 1: fused QKV projection (R13-exact structure; merged B ldsm_x4t).
// Block M=64 x N=128, k-chunk 32, 3-stage cp.async. Warps 2(M)x4(N).
//   As[64][40]  ([m][k])  A via ldsm_x4  |  Bs[32][136] ([k][n])  B via ldsm_x4t
// ---------------------------------------------------------------------------
#define QKV_A (64 * 40)
#define QKV_B (32 * 136)
#define QKV_STAGES 3
#define QKV_SMEM ((QKV_STAGES * (QKV_A + QKV_B)) * 2)
__global__ __launch_bounds__(256) void qkv_kernel(
    const float* __restrict__ bq, const float* __restrict__ bk,
    const float* __restrict__ bv)
{
    extern __shared__ bf16 sm[];
    bf16* As = sm;
    bf16* Bs = sm + QKV_STAGES * QKV_A;

    const int b  = blockIdx.z;
    const int rt = blockIdx.y;           // 0..9
    const int l0 = blockIdx.x * 128;

    const bf16* W; const float* bias; bf16* out; int row0; float osc;
    if (rt == 0)      { W = g_wq; bias = bq; out = g_qb + (size_t)b * CQ * LL; row0 = 0; osc = SCALE; }
    else if (rt == 1) { W = g_wk; bias = bk; out = g_kb + (size_t)b * CQ * LL; row0 = 0; osc = 1.f; }
    else              { W = g_wv; bias = bv; out = g_vb + (size_t)b * CC * LL; row0 = (rt - 2) * 64; osc = 1.f; }

    const int tid = threadIdx.x, w = tid >> 5, lane = tid & 31;
    const int g = lane >> 2, t = lane & 3;
    const int wm = (w >> 2) * 32, wn = (w & 3) * 32;
    const int l15 = lane & 15, hi = lane >> 4;
    const bf16* xb = g_xb + (size_t)b * CC * LL;
    const unsigned smA = (unsigned)__cvta_generic_to_shared(As);
    const unsigned smB = (unsigned)__cvta_generic_to_shared(Bs);

    float acc[2][4][4] = {};

    auto stage = [&](int buf, int k0) {
        bf16* Ab = As + buf * QKV_A;
        bf16* Bb = Bs + buf * QKV_B;
        {
            int m = tid >> 2, k8 = (tid & 3) * 8;
            cp16(Ab + m * 40 + k8, W + (size_t)(row0 + m) * CC + k0 + k8);
        }
        #pragma unroll
        for (int i = 0; i < 2; ++i) {
            int idx = tid + i * 256, k = idx >> 4, n8 = (idx & 15) * 8;
            cp16(Bb + k * 136 + n8, xb + (size_t)(k0 + k) * LL + l0 + n8);
        }
        CP_COMMIT();
    };

    const int NIT = CC / 32;   // 16
    stage(0, 0); stage(1, 32);
    int ld = 2, cb = 0;
    for (int it = 0; it < NIT; ++it) {
        if (it < NIT - 2) { CP_WAIT(1); } else { CP_WAIT(0); }
        __syncthreads();
        if (it + 2 < NIT) { stage(ld, (it + 2) * 32); ld = (ld == 2) ? 0 : ld + 1; }
        const unsigned a0 = smA + (unsigned)(cb * QKV_A) * 2;
        const unsigned b0a = smB + (unsigned)(cb * QKV_B) * 2;
        cb = (cb == 2) ? 0 : cb + 1;
        #pragma unroll
        for (int ks = 0; ks < 2; ++ks) {
            const int kk = ks * 16;
            unsigned af[2][4], bf[4][2];
            #pragma unroll
            for (int mi = 0; mi < 2; ++mi)
                ldsm_x4(af[mi], a0 + (unsigned)((wm + mi * 16 + l15) * 40 + kk) * 2 + hi * 16);
            #pragma unroll
            for (int ni = 0; ni < 4; ni += 2)   // merged: two B frags per ldsm_x4t
                ldsm_x4t(&bf[ni][0], b0a + (unsigned)((kk + l15) * 136 + wn + ni * 8 + hi * 8) * 2);
            #pragma unroll
            for (int mi = 0; mi < 2; ++mi)
                #pragma unroll
                for (int ni = 0; ni < 4; ++ni)
                    mma_bf16(acc[mi][ni], af[mi], bf[ni]);
        }
    }

    #pragma unroll
    for (int mi = 0; mi < 2; ++mi) {
        int r0r = row0 + wm + mi * 16 + g;
        int r1r = r0r + 8;
        float b0v = bias[r0r], b1v = bias[r1r];
        #pragma unroll
        for (int ni = 0; ni < 4; ++ni) {
            int col = l0 + wn + ni * 8 + 2 * t;
            *(bf162*)&out[(size_t)r0r * LL + col] =
                __floats2bfloat162_rn((acc[mi][ni][0] + b0v) * osc, (acc[mi][ni][1] + b0v) * osc);
            *(bf162*)&out[(size_t)r1r * LL + col] =
                __floats2bfloat162_rn((acc[mi][ni][2] + b1v) * osc, (acc[mi][ni][3] + b1v) * osc);
        }
    }
}

// ---------------------------------------------------------------------------
// Kernel 2: FUSED flash attention v2 (R13-exact) + skip-rescale guards.
// Block: 64 q-rows x full C=512, 256 threads (8 warps). Grid (32 q-tiles, 8 b).
//   warps 0-3: GEMM1 + online softmax (once), pack P C->A, store P + f to smem.
//   barrier; warps 4-7 read f / ldsm P; all 8 warps GEMM2 (16q x 256c each).
// acc *= f loops skipped when f == 1.0 for the whole warp (bit-exact skip).
// Smem: Qs[64][72] @0 | Ks[2][64][72] @4608 | Vs[2][512][72] @13824 |
//   Ps[64][72] @87552 | f[64],linv[64] fp32 @ elem 92160.
// ---------------------------------------------------------------------------
#define FA_SMEM (92160 * 2 + 512)
__global__ __launch_bounds__(256, 1) void fa_kernel()
{
    extern __shared__ bf16 sm[];
    bf16* Qs = sm;
    bf16* Ks = sm + 4608;
    bf16* Vs = sm + 13824;
    bf16* Ps = sm + 87552;
    float* fS   = (float*)(sm + 92160);
    float* linv = fS + 64;

    const int b  = blockIdx.y;
    const int q0 = blockIdx.x * 64;

    const int tid = threadIdx.x, w = tid >> 5, lane = tid & 31;
    const int g = lane >> 2, t = lane & 3;
    const int qg = (w & 3) * 16;      // this warp's q-group rows
    const int ch = (w >> 2) * 256;    // this warp's c-half
    const bf16* qb = g_qb + (size_t)b * CQ * LL;
    const bf16* kb = g_kb + (size_t)b * CQ * LL;
    const bf16* vb = g_vb + (size_t)b * CC * LL;

    const unsigned smQ = (unsigned)__cvta_generic_to_shared(Qs);
    const unsigned smK = (unsigned)__cvta_generic_to_shared(Ks);
    const unsigned smV = (unsigned)__cvta_generic_to_shared(Vs);
    const unsigned smP = (unsigned)__cvta_generic_to_shared(Ps);
    unsigned* Ps32 = (unsigned*)Ps;

    // per-lane ldsm address components (validated R11-R13)
    const int aq_row = (lane >> 4) * 8 + (lane & 7);        // Q x4t row(c)
    const int aq_col = qg + ((lane >> 3) & 1) * 8;          // Q x4t col(q)
    const int bk_row = ((lane >> 3) & 1) * 8 + (lane & 7);  // K x4t row(c)
    const int bk_csel = (lane >> 4) * 8;                    // K x4t +col(k)
    const int v_row  = ((lane >> 4) & 1) * 8 + (lane & 7);  // V x4 row(c) in 16-grp
    const int v_csel = ((lane >> 3) & 1) * 8;               // V x4 +col(k)
    const int p_row  = lane & 15, p_hi = (lane >> 4) * 8;   // P x4 (non-trans)

    // load Q tile [c=64][q=64] once
    #pragma unroll
    for (int i = 0; i < 2; ++i) {
        int idx = tid + i * 256, c = idx >> 3, q8 = (idx & 7) * 8;
        cp16(Qs + c * 72 + q8, qb + (size_t)c * LL + q0 + q8);
    }
    CP_COMMIT();

    auto stage = [&](int buf, int kt) {
        bf16* Kb = Ks + buf * 4608;
        bf16* Vb = Vs + buf * 36864;
        const int k0 = kt * 64;
        #pragma unroll
        for (int i = 0; i < 2; ++i) {         // K: 64c x 64k
            int idx = tid + i * 256, c = idx >> 3, k8 = (idx & 7) * 8;
            cp16(Kb + c * 72 + k8, kb + (size_t)c * LL + k0 + k8);
        }
        #pragma unroll
        for (int i = 0; i < 16; ++i) {        // V: 512c x 64k
            int idx = tid + i * 256, c = idx >> 3, k8 = (idx & 7) * 8;
            cp16(Vb + c * 72 + k8, vb + (size_t)c * LL + k0 + k8);
        }
        CP_COMMIT();
    };
    stage(0, 0); stage(1, 1);

    float acc[32][4] = {};
    float mx0 = -1e30f, mx1 = -1e30f, ls0 = 0.f, ls1 = 0.f;

    const int NIT = LL / 64;   // 32
    for (int it = 0; it < NIT; ++it) {
        if (it < NIT - 1) { CP_WAIT(1); } else { CP_WAIT(0); }
        __syncthreads();
        const int cb = it & 1;
        const unsigned k0s = smK + (unsigned)(cb * 4608) * 2;
        const unsigned v0s = smV + (unsigned)(cb * 36864) * 2;

        unsigned paf[4][4];

        if (w < 4) {
            // ---- GEMM1: S[16q][64k] ----
            float sf[8][4];
            #pragma unroll
            for (int ni = 0; ni < 8; ++ni)
                #pragma unroll
                for (int j = 0; j < 4; ++j) sf[ni][j] = 0.f;
            #pragma unroll
            for (int cs = 0; cs < 4; ++cs) {
                unsigned af[4];
                ldsm_x4t(af, smQ + (unsigned)((cs * 16 + aq_row) * 72 + aq_col) * 2);
                #pragma unroll
                for (int nj = 0; nj < 4; ++nj) {
                    unsigned bq4[4];
                    ldsm_x4t(bq4, k0s + (unsigned)((cs * 16 + bk_row) * 72 + nj * 16 + bk_csel) * 2);
                    mma_bf16(sf[2 * nj],     af, bq4);
                    mma_bf16(sf[2 * nj + 1], af, bq4 + 2);
                }
            }

            // ---- online softmax (rows qg+g, qg+g+8) ----
            float cm0 = -1e30f, cm1 = -1e30f;
            #pragma unroll
            for (int ni = 0; ni < 8; ++ni) {
                cm0 = fmaxf(cm0, fmaxf(sf[ni][0], sf[ni][1]));
                cm1 = fmaxf(cm1, fmaxf(sf[ni][2], sf[ni][3]));
            }
            cm0 = fmaxf(cm0, __shfl_xor_sync(0xffffffffu, cm0, 1));
            cm0 = fmaxf(cm0, __shfl_xor_sync(0xffffffffu, cm0, 2));
            cm1 = fmaxf(cm1, __shfl_xor_sync(0xffffffffu, cm1, 1));
            cm1 = fmaxf(cm1, __shfl_xor_sync(0xffffffffu, cm1, 2));
            const float mn0 = fmaxf(mx0, cm0), mn1 = fmaxf(mx1, cm1);
            const float f0 = __expf(mx0 - mn0), f1 = __expf(mx1 - mn1);
            mx0 = mn0; mx1 = mn1;

            float s0 = 0.f, s1 = 0.f;
            #pragma unroll
            for (int ni = 0; ni < 8; ++ni) {
                sf[ni][0] = __expf(sf[ni][0] - mn0);
                sf[ni][1] = __expf(sf[ni][1] - mn0);
                sf[ni][2] = __expf(sf[ni][2] - mn1);
                sf[ni][3] = __expf(sf[ni][3] - mn1);
                s0 += sf[ni][0] + sf[ni][1];
                s1 += sf[ni][2] + sf[ni][3];
            }
            s0 += __shfl_xor_sync(0xffffffffu, s0, 1);
            s0 += __shfl_xor_sync(0xffffffffu, s0, 2);
            s1 += __shfl_xor_sync(0xffffffffu, s1, 1);
            s1 += __shfl_xor_sync(0xffffffffu, s1, 2);
            ls0 = ls0 * f0 + s0;
            ls1 = ls1 * f1 + s1;

            // rescale own acc — skipped when f == 1.0 for the whole warp
            if (__any_sync(0xffffffffu, (f0 != 1.f) || (f1 != 1.f))) {
                #pragma unroll
                for (int ni = 0; ni < 32; ++ni) {
                    acc[ni][0] *= f0; acc[ni][1] *= f0;
                    acc[ni][2] *= f1; acc[ni][3] *= f1;
                }
            }

            // pack C->A and store packed P to smem (word stride 36)
            #pragma unroll
            for (int ks = 0; ks < 4; ++ks) {
                paf[ks][0] = packbf(sf[2 * ks][0],     sf[2 * ks][1]);
                paf[ks][1] = packbf(sf[2 * ks][2],     sf[2 * ks][3]);
                paf[ks][2] = packbf(sf[2 * ks + 1][0], sf[2 * ks + 1][1]);
                paf[ks][3] = packbf(sf[2 * ks + 1][2], sf[2 * ks + 1][3]);
                Ps32[(qg + g    ) * 36 + ks * 8 +     t] = paf[ks][0];
                Ps32[(qg + g + 8) * 36 + ks * 8 +     t] = paf[ks][1];
                Ps32[(qg + g    ) * 36 + ks * 8 + 4 + t] = paf[ks][2];
                Ps32[(qg + g + 8) * 36 + ks * 8 + 4 + t] = paf[ks][3];
            }
            if (t == 0) { fS[qg + g] = f0; fS[qg + g + 8] = f1; }
        }
        __syncthreads();

        if (w >= 4) {
            const float f0 = fS[qg + g], f1 = fS[qg + g + 8];
            if (__any_sync(0xffffffffu, (f0 != 1.f) || (f1 != 1.f))) {
                #pragma unroll
                for (int ni = 0; ni < 32; ++ni) {
                    acc[ni][0] *= f0; acc[ni][1] *= f0;
                    acc[ni][2] *= f1; acc[ni][3] *= f1;
                }
            }
            #pragma unroll
            for (int ks = 0; ks < 4; ++ks)
                ldsm_x4(paf[ks], smP + (unsigned)((qg + p_row) * 72 + ks * 16 + p_hi) * 2);
        }

        // ---- GEMM2: acc[16q][256c] += P[16q][64k] * V^T ----
        #pragma unroll
        for (int ks = 0; ks < 4; ++ks) {
            const int kk = ks * 16;
            #pragma unroll
            for (int ci = 0; ci < 16; ++ci) {
                unsigned vf[4];
                ldsm_x4(vf, v0s + (unsigned)((ch + ci * 16 + v_row) * 72 + kk + v_csel) * 2);
                mma_bf16(acc[2 * ci],     paf[ks], vf);
                mma_bf16(acc[2 * ci + 1], paf[ks], vf + 2);
            }
        }
        __syncthreads();
        if (it + 2 < NIT) stage(cb, it + 2);
    }

    // ---- epilogue ----
    if (w < 4 && t == 0) { linv[qg + g] = 1.f / ls0; linv[qg + g + 8] = 1.f / ls1; }
    __syncthreads();
    const float i0 = linv[qg + g], i1 = linv[qg + g + 8];
    const int row0 = q0 + qg + g, row1 = row0 + 8;
    bf16* ob0 = g_av2 + ((size_t)b * LL + row0) * CC;
    bf16* ob1 = g_av2 + ((size_t)b * LL + row1) * CC;
    #pragma unroll
    for (int ni = 0; ni < 32; ++ni) {
        int col = ch + ni * 8 + 2 * t;
        *(bf162*)&ob0[col] = __floats2bfloat162_rn(acc[ni][0] * i0, acc[ni][1] * i0);
        *(bf162*)&ob1[col] = __floats2bfloat162_rn(acc[ni][2] * i1, acc[ni][3] * i1);
    }
}

// ---------------------------------------------------------------------------
// Kernel 3: O projection + bias + residual (R13-exact; merged B ldsm_x4).
// Block 128o x 128l, k-chunk 32, 3-stage cp.async.
//   As[128][40] (Wo [o][c])  ldsm_x4  |  Bs[128][40] (av [l][c])  ldsm_x4 merged
// ---------------------------------------------------------------------------
#define OP_A (128 * 40)
#define OP_B (128 * 40)
#define OP_STAGES 3
#define OP_SMEM ((OP_STAGES * (OP_A + OP_B)) * 2)
__global__ __launch_bounds__(256) void outproj_kernel(
    const float* __restrict__ x,
    const float* __restrict__ bo, float* __restrict__ out)
{
    extern __shared__ bf16 sm[];
    bf16* As = sm;                      // [3][128][40]  Wo tile [o][c]
    bf16* Bs = sm + OP_STAGES * OP_A;   // [3][128][40]  av tile [l][c]

    const int b  = blockIdx.z;
    const int r0 = blockIdx.y * 128;
    const int l0 = blockIdx.x * 128;

    const int tid = threadIdx.x, w = tid >> 5, lane = tid & 31;
    const int g = lane >> 2, t = lane & 3;
    const int wm = (w >> 2) * 64, wn = (w & 3) * 32;
    const int l15 = lane & 15, hi = lane >> 4;
    const int l7 = lane & 7, b8 = ((lane >> 3) & 1) * 8;
    const bf16* avb = g_av2 + (size_t)b * LL * CC;
    const unsigned smA = (unsigned)__cvta_generic_to_shared(As);
    const unsigned smB = (unsigned)__cvta_generic_to_shared(Bs);

    float acc[4][4][4] = {};

    auto stage = [&](int buf, int k0) {
        bf16* Ab = As + buf * OP_A;
        bf16* Bb = Bs + buf * OP_B;
        #pragma unroll
        for (int i = 0; i < 2; ++i) {
            int idx = tid + i * 256, m = idx >> 2, k8 = (idx & 3) * 8;
            cp16(Ab + m * 40 + k8, g_wo + (size_t)(r0 + m) * CC + k0 + k8);
        }
        #pragma unroll
        for (int i = 0; i < 2; ++i) {
            int idx = tid + i * 256, l = idx >> 2, c8 = (idx & 3) * 8;
            cp16(Bb + l * 40 + c8, avb + (size_t)(l0 + l) * CC + k0 + c8);
        }
        CP_COMMIT();
    };

    const int NIT = CC / 32;   // 16
    stage(0, 0); stage(1, 32);
    int ld = 2, cb = 0;
    for (int it = 0; it < NIT; ++it) {
        if (it < NIT - 2) { CP_WAIT(1); } else { CP_WAIT(0); }
        __syncthreads();
        if (it + 2 < NIT) { stage(ld, (it + 2) * 32); ld = (ld == 2) ? 0 : ld + 1; }
        const unsigned a0 = smA + (unsigned)(cb * OP_A) * 2;
        const unsigned b0a = smB + (unsigned)(cb * OP_B) * 2;
        cb = (cb == 2) ? 0 : cb + 1;
        #pragma unroll
        for (int ks = 0; ks < 2; ++ks) {
            const int kk = ks * 16;
            unsigned af[4][4], bf[4][2];
            #pragma unroll
            for (int mi = 0; mi < 4; ++mi)
                ldsm_x4(af[mi], a0 + (unsigned)((wm + mi * 16 + l15) * 40 + kk) * 2 + hi * 16);
            #pragma unroll
            for (int ni = 0; ni < 4; ni += 2)   // merged: two B frags per ldsm_x4
                ldsm_x4(&bf[ni][0],
                    b0a + (unsigned)((wn + ni * 8 + hi * 8 + l7) * 40 + kk + b8) * 2);
            #pragma unroll
            for (int mi = 0; mi < 4; ++mi)
                #pragma unroll
                for (int ni = 0; ni < 4; ++ni)
                    mma_bf16(acc[mi][ni], af[mi], bf[ni]);
        }
    }

    #pragma unroll
    for (int mi = 0; mi < 4; ++mi) {
        int ch0 = r0 + wm + mi * 16 + g;
        int ch1 = ch0 + 8;
        float b0v = bo[ch0], b1v = bo[ch1];
        #pragma unroll
        for (int ni = 0; ni < 4; ++ni) {
            int col = l0 + wn + ni * 8 + 2 * t;
            size_t off0 = (size_t)b * CC * LL + (size_t)ch0 * LL + col;
            size_t off1 = (size_t)b * CC * LL + (size_t)ch1 * LL + col;
            float2 x0 = *(const float2*)&x[off0];
            float2 x1 = *(const float2*)&x[off1];
            *(float2*)&out[off0] = make_float2(acc[mi][ni][0] + b0v + x0.x,
                                               acc[mi][ni][1] + b0v + x0.y);
            *(float2*)&out[off1] = make_float2(acc[mi][ni][2] + b1v + x1.x,
                                               acc[mi][ni][3] + b1v + x1.y);
        }
    }
}

// ---------------------------------------------------------------------------
// Launch: 4 kernels on one stream, graph-capturable, no allocations.
// ---------------------------------------------------------------------------
extern "C" void kernel_launch(void* const* d_in, const int* in_sizes, int n_in,
                              void* d_out, int out_size)
{
    (void)in_sizes; (void)n_in; (void)out_size;
    const float* x  = (const float*)d_in[0];
    const float* Wq = (const float*)d_in[1];
    const float* bq = (const float*)d_in[2];
    const float* Wk = (const float*)d_in[3];
    const float* bk = (const float*)d_in[4];
    const float* Wv = (const float*)d_in[5];
    const float* bv = (const float*)d_in[6];
    const float* Wo = (const float*)d_in[7];
    const float* bo = (const float*)d_in[8];
    float* out = (float*)d_out;

    cudaFuncSetAttribute(qkv_kernel,     cudaFuncAttributeMaxDynamicSharedMemorySize, QKV_SMEM);
    cudaFuncSetAttribute(fa_kernel,      cudaFuncAttributeMaxDynamicSharedMemorySize, FA_SMEM);
    cudaFuncSetAttribute(outproj_kernel, cudaFuncAttributeMaxDynamicSharedMemorySize, OP_SMEM);

    dim3 blk(256);
    cvt_kernel    <<<(unsigned)((CVT_PAIRS + 255) / 256), blk>>>(x, Wq, Wk, Wv, Wo);
    qkv_kernel    <<<dim3(LL / 128, 10,       BB), blk, QKV_SMEM>>>(bq, bk, bv);
    fa_kernel     <<<dim3(LL / 64,  BB          ), blk, FA_SMEM>>>();
    outproj_kernel<<<dim3(LL / 128, CC / 128, BB), blk, OP_SMEM>>>(x, bo, out);
}

// round 17
// speedup vs baseline: 1.7848x; 1.0162x over previous
#include <cuda_runtime.h>
#include <cuda_bf16.h>

// Shapes (fixed by the problem)
#define BB  8
#define CC  512
#define LL  2048
#define CQ  64
#define SCALE 0.125f   // CQK^-0.5 (exact power of 2; folded into q at qkv epilogue)

typedef __nv_bfloat16  bf16;
typedef __nv_bfloat162 bf162;

// ---------------------------------------------------------------------------
// Scratch (static __device__ arrays — no allocation anywhere)
// ---------------------------------------------------------------------------
__device__ bf16 g_xb[(size_t)BB * CC * LL];        // 16.8 MB  x in bf16
__device__ bf16 g_wq[CQ * CC], g_wk[CQ * CC];      // 64 KB each
__device__ bf16 g_wv[(size_t)CC * CC];             // 512 KB
__device__ bf16 g_wo[(size_t)CC * CC];             // 512 KB
__device__ bf16 g_qb[(size_t)BB * CQ * LL];        // 2 MB   (pre-scaled by SCALE)
__device__ bf16 g_kb[(size_t)BB * CQ * LL];        // 2 MB
__device__ bf16 g_vb[(size_t)BB * CC * LL];        // 16.8 MB
__device__ bf16 g_av2[(size_t)BB * LL * CC];       // 16.8 MB  attention out, [b][l][c]

// ---------------------------------------------------------------------------
// Helpers
// ---------------------------------------------------------------------------
__device__ __forceinline__ void cp16(void* dst_smem, const void* src) {
    unsigned d = (unsigned)__cvta_generic_to_shared(dst_smem);
    asm volatile("cp.async.cg.shared.global [%0], [%1], 16;" :: "r"(d), "l"(src));
}
#define CP_COMMIT() asm volatile("cp.async.commit_group;")
#define CP_WAIT(N)  asm volatile("cp.async.wait_group " #N ";")

__device__ __forceinline__ void ldsm_x4(unsigned* r, unsigned s) {
    asm volatile("ldmatrix.sync.aligned.m8n8.x4.shared.b16 {%0,%1,%2,%3}, [%4];"
        : "=r"(r[0]), "=r"(r[1]), "=r"(r[2]), "=r"(r[3]) : "r"(s));
}
__device__ __forceinline__ void ldsm_x4t(unsigned* r, unsigned s) {
    asm volatile("ldmatrix.sync.aligned.m8n8.x4.trans.shared.b16 {%0,%1,%2,%3}, [%4];"
        : "=r"(r[0]), "=r"(r[1]), "=r"(r[2]), "=r"(r[3]) : "r"(s));
}

// D += A(16x16 row) * B(16x8 col), fp32 accum.
__device__ __forceinline__ void mma_bf16(float* c, const unsigned* a, const unsigned* b) {
    asm volatile(
        "mma.sync.aligned.m16n8k16.row.col.f32.bf16.bf16.f32 "
        "{%0,%1,%2,%3}, {%4,%5,%6,%7}, {%8,%9}, {%0,%1,%2,%3};"
        : "+f"(c[0]), "+f"(c[1]), "+f"(c[2]), "+f"(c[3])
        : "r"(a[0]), "r"(a[1]), "r"(a[2]), "r"(a[3]), "r"(b[0]), "r"(b[1]));
}

// pack two fp32 into one bf16x2 reg: low = lo, high = hi
__device__ __forceinline__ unsigned packbf(float lo, float hi) {
    unsigned d;
    asm("cvt.rn.bf16x2.f32 %0, %1, %2;" : "=r"(d) : "f"(hi), "f"(lo));
    return d;
}

// Frag maps (lane = 4g+t):
//  A: a0=A[g][2t,2t+1] a1=A[g+8][2t..] a2=A[g][8+2t..] a3=A[g+8][8+2t..]
//  B: b0=B[2t,2t+1][g] b1=B[8+2t..][g]   (B indexed [k][n])
//  C: c0=C[g][2t] c1=C[g][2t+1] c2=C[g+8][2t] c3=C[g+8][2t+1]
// C->A identity: two adjacent n8 C tiles == one k16 A frag (the FA2 trick).
// Smem strides 40/72/136 bf16 = 5/9/17 x16B units -> rows mod 8 distinct, LDSM-safe.

// ---------------------------------------------------------------------------
// Kernel 0: fp32 -> bf16 conversion of x and weights (once per launch)
// ---------------------------------------------------------------------------
#define NX  ((size_t)BB * CC * LL)
#define NWQ ((size_t)CQ * CC)
#define NWV ((size_t)CC * CC)
#define CVT_PAIRS ((NX + 2 * NWQ + 2 * NWV) / 2)
__global__ __launch_bounds__(256) void cvt_kernel(
    const float* __restrict__ x,  const float* __restrict__ Wq,
    const float* __restrict__ Wk, const float* __restrict__ Wv,
    const float* __restrict__ Wo)
{
    size_t i = ((size_t)blockIdx.x * 256 + threadIdx.x) * 2;
    if (i < NX) {
        *(bf162*)&g_xb[i] = __float22bfloat162_rn(*(const float2*)&x[i]); return;
    }
    i -= NX;
    if (i < NWQ) { *(bf162*)&g_wq[i] = __float22bfloat162_rn(*(const float2*)&Wq[i]); return; }
    i -= NWQ;
    if (i < NWQ) { *(bf162*)&g_wk[i] = __float22bfloat162_rn(*(const float2*)&Wk[i]); return; }
    i -= NWQ;
    if (i < NWV) { *(bf162*)&g_wv[i] = __float22bfloat162_rn(*(const float2*)&Wv[i]); return; }
    i -= NWV;
    if (i < NWV) { *(bf162*)&g_wo[i] = __float22bfloat162_rn(*(const float2*)&Wo[i]); }
}

// ---------------------------------------------------------------------------
// Kernel 1: fused QKV projection. R13 tiles/strides, now 2-stage (28 KB smem
// -> 2 CTAs/SM). Block M=64 x N=128, k-chunk 32. Warps 2(M)x4(N).
//   As[64][40]  ([m][k])  A via ldsm_x4  |  Bs[32][136] ([k][n])  B via ldsm_x4t
// ---------------------------------------------------------------------------
#define QKV_A (64 * 40)
#define QKV_B (32 * 136)
#define QKV_SMEM ((2 * (QKV_A + QKV_B)) * 2)
__global__ __launch_bounds__(256) void qkv_kernel(
    const float* __restrict__ bq, const float* __restrict__ bk,
    const float* __restrict__ bv)
{
    extern __shared__ bf16 sm[];
    bf16* As = sm;
    bf16* Bs = sm + 2 * QKV_A;

    const int b  = blockIdx.z;
    const int rt = blockIdx.y;           // 0..9
    const int l0 = blockIdx.x * 128;

    const bf16* W; const float* bias; bf16* out; int row0; float osc;
    if (rt == 0)      { W = g_wq; bias = bq; out = g_qb + (size_t)b * CQ * LL; row0 = 0; osc = SCALE; }
    else if (rt == 1) { W = g_wk; bias = bk; out = g_kb + (size_t)b * CQ * LL; row0 = 0; osc = 1.f; }
    else              { W = g_wv; bias = bv; out = g_vb + (size_t)b * CC * LL; row0 = (rt - 2) * 64; osc = 1.f; }

    const int tid = threadIdx.x, w = tid >> 5, lane = tid & 31;
    const int g = lane >> 2, t = lane & 3;
    const int wm = (w >> 2) * 32, wn = (w & 3) * 32;
    const int l15 = lane & 15, hi = lane >> 4;
    const bf16* xb = g_xb + (size_t)b * CC * LL;
    const unsigned smA = (unsigned)__cvta_generic_to_shared(As);
    const unsigned smB = (unsigned)__cvta_generic_to_shared(Bs);

    float acc[2][4][4] = {};

    auto stage = [&](int buf, int k0) {
        bf16* Ab = As + buf * QKV_A;
        bf16* Bb = Bs + buf * QKV_B;
        {
            int m = tid >> 2, k8 = (tid & 3) * 8;
            cp16(Ab + m * 40 + k8, W + (size_t)(row0 + m) * CC + k0 + k8);
        }
        #pragma unroll
        for (int i = 0; i < 2; ++i) {
            int idx = tid + i * 256, k = idx >> 4, n8 = (idx & 15) * 8;
            cp16(Bb + k * 136 + n8, xb + (size_t)(k0 + k) * LL + l0 + n8);
        }
        CP_COMMIT();
    };

    const int NIT = CC / 32;   // 16
    stage(0, 0); stage(1, 32);
    for (int it = 0; it < NIT; ++it) {
        if (it < NIT - 1) { CP_WAIT(1); } else { CP_WAIT(0); }
        __syncthreads();
        const int cb = it & 1;
        const unsigned a0 = smA + (unsigned)(cb * QKV_A) * 2;
        const unsigned b0a = smB + (unsigned)(cb * QKV_B) * 2;
        #pragma unroll
        for (int ks = 0; ks < 2; ++ks) {
            const int kk = ks * 16;
            unsigned af[2][4], bf[4][2];
            #pragma unroll
            for (int mi = 0; mi < 2; ++mi)
                ldsm_x4(af[mi], a0 + (unsigned)((wm + mi * 16 + l15) * 40 + kk) * 2 + hi * 16);
            #pragma unroll
            for (int ni = 0; ni < 4; ni += 2)   // merged: two B frags per ldsm_x4t
                ldsm_x4t(&bf[ni][0], b0a + (unsigned)((kk + l15) * 136 + wn + ni * 8 + hi * 8) * 2);
            #pragma unroll
            for (int mi = 0; mi < 2; ++mi)
                #pragma unroll
                for (int ni = 0; ni < 4; ++ni)
                    mma_bf16(acc[mi][ni], af[mi], bf[ni]);
        }
        __syncthreads();
        if (it + 2 < NIT) stage(cb, (it + 2) * 32);
    }

    #pragma unroll
    for (int mi = 0; mi < 2; ++mi) {
        int r0r = row0 + wm + mi * 16 + g;
        int r1r = r0r + 8;
        float b0v = bias[r0r], b1v = bias[r1r];
        #pragma unroll
        for (int ni = 0; ni < 4; ++ni) {
            int col = l0 + wn + ni * 8 + 2 * t;
            *(bf162*)&out[(size_t)r0r * LL + col] =
                __floats2bfloat162_rn((acc[mi][ni][0] + b0v) * osc, (acc[mi][ni][1] + b0v) * osc);
            *(bf162*)&out[(size_t)r1r * LL + col] =
                __floats2bfloat162_rn((acc[mi][ni][2] + b1v) * osc, (acc[mi][ni][3] + b1v) * osc);
        }
    }
}

// ---------------------------------------------------------------------------
// Kernel 2: FUSED flash attention v4 — symmetric warps, zero P exchange.
// Block: 128 q-rows x 256 c, 256 threads (8 warps), qg = w*16: each warp owns
// DISTINCT 16 q-rows. Per 64-k tile every warp: GEMM1 S[16q][64k] for its own
// rows -> online softmax (own rows, lanes t0-3 shfl) -> pack P C->A in reg ->
// GEMM2 acc[16q][256c] += P * V^T. No phase split, no smem P/f, 2 barriers.
// Grid (16 q-tiles, 2 c-halves, 8 b) = 256 blocks. GEMM1 redundancy 2x
// (across c-halves) = same total as v2's non-redundant-but-half-warps scheme.
// Smem: Qs[64][136] @0 | Ks[2][64][72] | Vs[2][256][72]  = 107 KB, 1 CTA/SM.
// ---------------------------------------------------------------------------
#define FA_Q (64 * 136)
#define FA_K (64 * 72)
#define FA_V (256 * 72)
#define FA_SMEM ((FA_Q + 2 * (FA_K + FA_V)) * 2)
__global__ __launch_bounds__(256, 1) void fa_kernel()
{
    extern __shared__ bf16 sm[];
    bf16* Qs = sm;
    bf16* Ks = sm + FA_Q;
    bf16* Vs = sm + FA_Q + 2 * FA_K;

    const int b  = blockIdx.z;
    const int q0 = blockIdx.x * 128;
    const int c0 = blockIdx.y * 256;

    const int tid = threadIdx.x, w = tid >> 5, lane = tid & 31;
    const int g = lane >> 2, t = lane & 3;
    const int qg = w * 16;            // warp's own q-rows (all 8 distinct)
    const bf16* qb = g_qb + (size_t)b * CQ * LL;
    const bf16* kb = g_kb + (size_t)b * CQ * LL;
    const bf16* vb = g_vb + (size_t)b * CC * LL + (size_t)c0 * LL;

    const unsigned smQ = (unsigned)__cvta_generic_to_shared(Qs);
    const unsigned smK = (unsigned)__cvta_generic_to_shared(Ks);
    const unsigned smV = (unsigned)__cvta_generic_to_shared(Vs);

    // per-lane ldsm address components (patterns validated R11-R16)
    const int aq_row = (lane >> 4) * 8 + (lane & 7);        // Q x4t row(c)
    const int aq_col = qg + ((lane >> 3) & 1) * 8;          // Q x4t col(q)
    const int bk_row = ((lane >> 3) & 1) * 8 + (lane & 7);  // K x4t row(c)
    const int bk_csel = (lane >> 4) * 8;                    // K x4t +col(k)
    const int v_row  = ((lane >> 4) & 1) * 8 + (lane & 7);  // V x4 row(c) in 16-grp
    const int v_csel = ((lane >> 3) & 1) * 8;               // V x4 +col(k)

    // load Q tile [c=64][q=128] once (stride 136)
    #pragma unroll
    for (int i = 0; i < 4; ++i) {
        int idx = tid + i * 256, c = idx >> 4, q8 = (idx & 15) * 8;
        cp16(Qs + c * 136 + q8, qb + (size_t)c * LL + q0 + q8);
    }
    CP_COMMIT();

    auto stage = [&](int buf, int kt) {
        bf16* Kb = Ks + buf * FA_K;
        bf16* Vb = Vs + buf * FA_V;
        const int k0 = kt * 64;
        #pragma unroll
        for (int i = 0; i < 2; ++i) {         // K: 64c x 64k
            int idx = tid + i * 256, c = idx >> 3, k8 = (idx & 7) * 8;
            cp16(Kb + c * 72 + k8, kb + (size_t)c * LL + k0 + k8);
        }
        #pragma unroll
        for (int i = 0; i < 8; ++i) {         // V: 256c x 64k
            int idx = tid + i * 256, c = idx >> 3, k8 = (idx & 7) * 8;
            cp16(Vb + c * 72 + k8, vb + (size_t)c * LL + k0 + k8);
        }
        CP_COMMIT();
    };
    stage(0, 0); stage(1, 1);

    float acc[32][4] = {};
    float mx0 = -1e30f, mx1 = -1e30f, ls0 = 0.f, ls1 = 0.f;

    const int NIT = LL / 64;   // 32
    for (int it = 0; it < NIT; ++it) {
        if (it < NIT - 1) { CP_WAIT(1); } else { CP_WAIT(0); }
        __syncthreads();
        const int cb = it & 1;
        const unsigned k0s = smK + (unsigned)(cb * FA_K) * 2;
        const unsigned v0s = smV + (unsigned)(cb * FA_V) * 2;

        // ---- GEMM1: S[16q][64k] for this warp's own q-rows ----
        float sf[8][4];
        #pragma unroll
        for (int ni = 0; ni < 8; ++ni)
            #pragma unroll
            for (int j = 0; j < 4; ++j) sf[ni][j] = 0.f;
        #pragma unroll
        for (int cs = 0; cs < 4; ++cs) {
            unsigned af[4];
            ldsm_x4t(af, smQ + (unsigned)((cs * 16 + aq_row) * 136 + aq_col) * 2);
            #pragma unroll
            for (int nj = 0; nj < 4; ++nj) {
                unsigned bq4[4];
                ldsm_x4t(bq4, k0s + (unsigned)((cs * 16 + bk_row) * 72 + nj * 16 + bk_csel) * 2);
                mma_bf16(sf[2 * nj],     af, bq4);
                mma_bf16(sf[2 * nj + 1], af, bq4 + 2);
            }
        }

        // ---- online softmax (rows qg+g, qg+g+8) ----
        float cm0 = -1e30f, cm1 = -1e30f;
        #pragma unroll
        for (int ni = 0; ni < 8; ++ni) {
            cm0 = fmaxf(cm0, fmaxf(sf[ni][0], sf[ni][1]));
            cm1 = fmaxf(cm1, fmaxf(sf[ni][2], sf[ni][3]));
        }
        cm0 = fmaxf(cm0, __shfl_xor_sync(0xffffffffu, cm0, 1));
        cm0 = fmaxf(cm0, __shfl_xor_sync(0xffffffffu, cm0, 2));
        cm1 = fmaxf(cm1, __shfl_xor_sync(0xffffffffu, cm1, 1));
        cm1 = fmaxf(cm1, __shfl_xor_sync(0xffffffffu, cm1, 2));
        const float mn0 = fmaxf(mx0, cm0), mn1 = fmaxf(mx1, cm1);
        const float f0 = __expf(mx0 - mn0), f1 = __expf(mx1 - mn1);
        mx0 = mn0; mx1 = mn1;

        float s0 = 0.f, s1 = 0.f;
        #pragma unroll
        for (int ni = 0; ni < 8; ++ni) {
            sf[ni][0] = __expf(sf[ni][0] - mn0);
            sf[ni][1] = __expf(sf[ni][1] - mn0);
            sf[ni][2] = __expf(sf[ni][2] - mn1);
            sf[ni][3] = __expf(sf[ni][3] - mn1);
            s0 += sf[ni][0] + sf[ni][1];
            s1 += sf[ni][2] + sf[ni][3];
        }
        s0 += __shfl_xor_sync(0xffffffffu, s0, 1);
        s0 += __shfl_xor_sync(0xffffffffu, s0, 2);
        s1 += __shfl_xor_sync(0xffffffffu, s1, 1);
        s1 += __shfl_xor_sync(0xffffffffu, s1, 2);
        ls0 = ls0 * f0 + s0;
        ls1 = ls1 * f1 + s1;

        // rescale acc — skipped when f == 1.0 for the whole warp (bit-exact)
        if (__any_sync(0xffffffffu, (f0 != 1.f) || (f1 != 1.f))) {
            #pragma unroll
            for (int ni = 0; ni < 32; ++ni) {
                acc[ni][0] *= f0; acc[ni][1] *= f0;
                acc[ni][2] *= f1; acc[ni][3] *= f1;
            }
        }

        // pack P: C-frags -> A-frags (in register, own rows)
        unsigned paf[4][4];
        #pragma unroll
        for (int ks = 0; ks < 4; ++ks) {
            paf[ks][0] = packbf(sf[2 * ks][0],     sf[2 * ks][1]);
            paf[ks][1] = packbf(sf[2 * ks][2],     sf[2 * ks][3]);
            paf[ks][2] = packbf(sf[2 * ks + 1][0], sf[2 * ks + 1][1]);
            paf[ks][3] = packbf(sf[2 * ks + 1][2], sf[2 * ks + 1][3]);
        }

        // ---- GEMM2: acc[16q][256c] += P[16q][64k] * V^T ----
        #pragma unroll
        for (int ks = 0; ks < 4; ++ks) {
            const int kk = ks * 16;
            #pragma unroll
            for (int ci = 0; ci < 16; ++ci) {
                unsigned vf[4];
                ldsm_x4(vf, v0s + (unsigned)((ci * 16 + v_row) * 72 + kk + v_csel) * 2);
                mma_bf16(acc[2 * ci],     paf[ks], vf);
                mma_bf16(acc[2 * ci + 1], paf[ks], vf + 2);
            }
        }
        __syncthreads();
        if (it + 2 < NIT) stage(cb, it + 2);
    }

    // ---- epilogue: divide by own l, write av [b][l][c] ----
    const float i0 = 1.0f / ls0, i1 = 1.0f / ls1;
    const int row0 = q0 + qg + g, row1 = row0 + 8;
    bf16* ob0 = g_av2 + ((size_t)b * LL + row0) * CC;
    bf16* ob1 = g_av2 + ((size_t)b * LL + row1) * CC;
    #pragma unroll
    for (int ni = 0; ni < 32; ++ni) {
        int col = c0 + ni * 8 + 2 * t;
        *(bf162*)&ob0[col] = __floats2bfloat162_rn(acc[ni][0] * i0, acc[ni][1] * i0);
        *(bf162*)&ob1[col] = __floats2bfloat162_rn(acc[ni][2] * i1, acc[ni][3] * i1);
    }
}

// ---------------------------------------------------------------------------
// Kernel 3: O projection + bias + residual. R13 tiles/strides, now 2-stage
// (41 KB smem -> 2 CTAs/SM). Block 128o x 128l, k-chunk 32.
//   As[128][40] (Wo [o][c])  ldsm_x4  |  Bs[128][40] (av [l][c])  ldsm_x4 merged
// ---------------------------------------------------------------------------
#define OP_A (128 * 40)
#define OP_B (128 * 40)
#define OP_SMEM ((2 * (OP_A + OP_B)) * 2)
__global__ __launch_bounds__(256) void outproj_kernel(
    const float* __restrict__ x,
    const float* __restrict__ bo, float* __restrict__ out)
{
    extern __shared__ bf16 sm[];
    bf16* As = sm;                 // [2][128][40]  Wo tile [o][c]
    bf16* Bs = sm + 2 * OP_A;      // [2][128][40]  av tile [l][c]

    const int b  = blockIdx.z;
    const int r0 = blockIdx.y * 128;
    const int l0 = blockIdx.x * 128;

    const int tid = threadIdx.x, w = tid >> 5, lane = tid & 31;
    const int g = lane >> 2, t = lane & 3;
    const int wm = (w >> 2) * 64, wn = (w & 3) * 32;
    const int l15 = lane & 15, hi = lane >> 4;
    const int l7 = lane & 7, b8 = ((lane >> 3) & 1) * 8;
    const bf16* avb = g_av2 + (size_t)b * LL * CC;
    const unsigned smA = (unsigned)__cvta_generic_to_shared(As);
    const unsigned smB = (unsigned)__cvta_generic_to_shared(Bs);

    float acc[4][4][4] = {};

    auto stage = [&](int buf, int k0) {
        bf16* Ab = As + buf * OP_A;
        bf16* Bb = Bs + buf * OP_B;
        #pragma unroll
        for (int i = 0; i < 2; ++i) {
            int idx = tid + i * 256, m = idx >> 2, k8 = (idx & 3) * 8;
            cp16(Ab + m * 40 + k8, g_wo + (size_t)(r0 + m) * CC + k0 + k8);
        }
        #pragma unroll
        for (int i = 0; i < 2; ++i) {
            int idx = tid + i * 256, l = idx >> 2, c8 = (idx & 3) * 8;
            cp16(Bb + l * 40 + c8, avb + (size_t)(l0 + l) * CC + k0 + c8);
        }
        CP_COMMIT();
    };

    const int NIT = CC / 32;   // 16
    stage(0, 0); stage(1, 32);
    for (int it = 0; it < NIT; ++it) {
        if (it < NIT - 1) { CP_WAIT(1); } else { CP_WAIT(0); }
        __syncthreads();
        const int cb = it & 1;
        const unsigned a0 = smA + (unsigned)(cb * OP_A) * 2;
        const unsigned b0a = smB + (unsigned)(cb * OP_B) * 2;
        #pragma unroll
        for (int ks = 0; ks < 2; ++ks) {
            const int kk = ks * 16;
            unsigned af[4][4], bf[4][2];
            #pragma unroll
            for (int mi = 0; mi < 4; ++mi)
                ldsm_x4(af[mi], a0 + (unsigned)((wm + mi * 16 + l15) * 40 + kk) * 2 + hi * 16);
            #pragma unroll
            for (int ni = 0; ni < 4; ni += 2)   // merged: two B frags per ldsm_x4
                ldsm_x4(&bf[ni][0],
                    b0a + (unsigned)((wn + ni * 8 + hi * 8 + l7) * 40 + kk + b8) * 2);
            #pragma unroll
            for (int mi = 0; mi < 4; ++mi)
                #pragma unroll
                for (int ni = 0; ni < 4; ++ni)
                    mma_bf16(acc[mi][ni], af[mi], bf[ni]);
        }
        __syncthreads();
        if (it + 2 < NIT) stage(cb, (it + 2) * 32);
    }

    #pragma unroll
    for (int mi = 0; mi < 4; ++mi) {
        int ch0 = r0 + wm + mi * 16 + g;
        int ch1 = ch0 + 8;
        float b0v = bo[ch0], b1v = bo[ch1];
        #pragma unroll
        for (int ni = 0; ni < 4; ++ni) {
            int col = l0 + wn + ni * 8 + 2 * t;
            size_t off0 = (size_t)b * CC * LL + (size_t)ch0 * LL + col;
            size_t off1 = (size_t)b * CC * LL + (size_t)ch1 * LL + col;
            float2 x0 = *(const float2*)&x[off0];
            float2 x1 = *(const float2*)&x[off1];
            *(float2*)&out[off0] = make_float2(acc[mi][ni][0] + b0v + x0.x,
                                               acc[mi][ni][1] + b0v + x0.y);
            *(float2*)&out[off1] = make_float2(acc[mi][ni][2] + b1v + x1.x,
                                               acc[mi][ni][3] + b1v + x1.y);
        }
    }
}

// ---------------------------------------------------------------------------
// Launch: 4 kernels on one stream, graph-capturable, no allocations.
// ---------------------------------------------------------------------------
extern "C" void kernel_launch(void* const* d_in, const int* in_sizes, int n_in,
                              void* d_out, int out_size)
{
    (void)in_sizes; (void)n_in; (void)out_size;
    const float* x  = (const float*)d_in[0];
    const float* Wq = (const float*)d_in[1];
    const float* bq = (const float*)d_in[2];
    const float* Wk = (const float*)d_in[3];
    const float* bk = (const float*)d_in[4];
    const float* Wv = (const float*)d_in[5];
    const float* bv = (const float*)d_in[6];
    const float* Wo = (const float*)d_in[7];
    const float* bo = (const float*)d_in[8];
    float* out = (float*)d_out;

    cudaFuncSetAttribute(qkv_kernel,     cudaFuncAttributeMaxDynamicSharedMemorySize, QKV_SMEM);
    cudaFuncSetAttribute(fa_kernel,      cudaFuncAttributeMaxDynamicSharedMemorySize, FA_SMEM);
    cudaFuncSetAttribute(outproj_kernel, cudaFuncAttributeMaxDynamicSharedMemorySize, OP_SMEM);

    dim3 blk(256);
    cvt_kernel    <<<(unsigned)((CVT_PAIRS + 255) / 256), blk>>>(x, Wq, Wk, Wv, Wo);
    qkv_kernel    <<<dim3(LL / 128, 10,       BB), blk, QKV_SMEM>>>(bq, bk, bv);
    fa_kernel     <<<dim3(LL / 128, 2,        BB), blk, FA_SMEM>>>();
    outproj_kernel<<<dim3(LL / 128, CC / 128, BB), blk, OP_SMEM>>>(x, bo, out);
}